// round 7
// baseline (speedup 1.0000x reference)
#include <cuda_runtime.h>

// ---------------- problem constants ----------------
constexpr int Bb = 4, Tt = 2048, Ssq = 2048, Ee = 512, Hh = 8, Dd = 64;
constexpr int BT = Bb * Tt;

// ---------------- device scratch (no cudaMalloc allowed) ----------------
__device__ float g_q[(size_t)Bb * Hh * Tt * Dd];       // [B,H,T,64], pre-scaled
__device__ float g_k[(size_t)Bb * Hh * Ssq * Dd];      // [B,H,S,64]
__device__ float g_v[(size_t)Bb * Hh * Ssq * Dd];      // [B,H,S,64]
__device__ float g_attnout[(size_t)BT * Ee];           // [B,T,E] pre-output-proj
__device__ float g_rowm[(size_t)Bb * Hh * Tt];         // per-row softmax max
__device__ float g_rowl[(size_t)Bb * Hh * Tt];         // per-row softmax denom

// ---------------- SGEMM: C = A[M,K] @ W[K,N] + bias, optional head layout ----------------
constexpr int BM = 128, BN = 128, BKk = 8, TM = 8, TN = 8;

__global__ __launch_bounds__(256, 2) void sgemm_bias(
    const float* __restrict__ A, const float* __restrict__ W,
    const float* __restrict__ bias, float* __restrict__ C,
    float scale, int head_layout)
{
    __shared__ float As[BKk][BM];
    __shared__ float Ws[BKk][BN];
    const int K = Ee, N = Ee;
    const int tid  = threadIdx.x;
    const int tcol = tid & 15;        // 16 col-groups
    const int trow = tid >> 4;        // 16 row-groups
    const int aRow = tid >> 1;        // 0..127
    const int aCol = (tid & 1) * 4;   // 0 or 4
    const int wRow = tid >> 5;        // 0..7
    const int wCol = (tid & 31) * 4;  // 0..124

    const float* Ab = A + (size_t)blockIdx.y * BM * K;
    const float* Wb = W + blockIdx.x * BN;

    float acc[TM][TN];
#pragma unroll
    for (int i = 0; i < TM; i++)
#pragma unroll
        for (int j = 0; j < TN; j++) acc[i][j] = 0.f;

    for (int k0 = 0; k0 < K; k0 += BKk) {
        float4 av = *(const float4*)(Ab + (size_t)aRow * K + k0 + aCol);
        As[aCol + 0][aRow] = av.x;
        As[aCol + 1][aRow] = av.y;
        As[aCol + 2][aRow] = av.z;
        As[aCol + 3][aRow] = av.w;
        *(float4*)(&Ws[wRow][wCol]) = *(const float4*)(Wb + (size_t)(k0 + wRow) * N + wCol);
        __syncthreads();
#pragma unroll
        for (int k = 0; k < BKk; k++) {
            float4 a0 = *(const float4*)&As[k][trow * TM];
            float4 a1 = *(const float4*)&As[k][trow * TM + 4];
            float4 b0 = *(const float4*)&Ws[k][tcol * TN];
            float4 b1 = *(const float4*)&Ws[k][tcol * TN + 4];
            float ar[8] = {a0.x, a0.y, a0.z, a0.w, a1.x, a1.y, a1.z, a1.w};
            float br[8] = {b0.x, b0.y, b0.z, b0.w, b1.x, b1.y, b1.z, b1.w};
#pragma unroll
            for (int i = 0; i < TM; i++)
#pragma unroll
                for (int j = 0; j < TN; j++) acc[i][j] = fmaf(ar[i], br[j], acc[i][j]);
        }
        __syncthreads();
    }

#pragma unroll
    for (int i = 0; i < TM; i++) {
        int m = blockIdx.y * BM + trow * TM + i;
        int b = m / Tt, t = m % Tt;
#pragma unroll
        for (int j = 0; j < TN; j++) {
            int n = blockIdx.x * BN + tcol * TN + j;
            float v = (acc[i][j] + bias[n]) * scale;
            if (head_layout) {
                int h = n >> 6, d = n & 63;
                C[((size_t)(b * Hh + h) * Tt + t) * Dd + d] = v;
            } else {
                C[(size_t)m * N + n] = v;
            }
        }
    }
}

// ---------------- fused attention: QK^T + masks + raw-score store + online softmax + PV ----------------
constexpr int QT = 64, SC = 128;
constexpr int QS_LD = 68, KS_LD = 129, PS_LD = 65, RED_LD = 17;
constexpr int ATT_SMEM_FLOATS =
    Dd * QS_LD + Dd * KS_LD + SC * Dd + SC * PS_LD + QT * RED_LD + 3 * QT;
constexpr int ATT_SMEM_BYTES = ATT_SMEM_FLOATS * 4;  // 121600 B

__global__ __launch_bounds__(256, 1) void attn_kernel(
    const unsigned char* __restrict__ kpm,    // [B,S] bool
    const unsigned char* __restrict__ amask,  // [T,S] bool
    float* __restrict__ attnw)                // raw-score scratch / attn output (may be null)
{
    extern __shared__ float sm[];
    float* Qs  = sm;                     // [Dd][QS_LD]  q transposed (d-major)
    float* Ks  = Qs + Dd * QS_LD;        // [Dd][KS_LD]  k transposed (d-major)
    float* Vs  = Ks + Dd * KS_LD;        // [SC][Dd]
    float* Ps  = Vs + SC * Dd;           // [SC][PS_LD]  p transposed (s-major)
    float* red = Ps + SC * PS_LD;        // [QT][RED_LD]
    float* m_s = red + QT * RED_LD;      // [QT]
    float* l_s = m_s + QT;               // [QT]
    float* f_s = l_s + QT;               // [QT]

    const int b  = blockIdx.z, h = blockIdx.y;
    const int t0 = blockIdx.x * QT;
    const int tid = threadIdx.x;
    const int tx  = tid & 15, ty = tid >> 4;
    const int r   = tid >> 4;
    const int d4  = (tid & 15) * 4;

    const float* qptr  = g_q + ((size_t)(b * Hh + h) * Tt + t0) * Dd;
    const float* kbase = g_k + (size_t)(b * Hh + h) * Ssq * Dd;
    const float* vbase = g_v + (size_t)(b * Hh + h) * Ssq * Dd;
    const unsigned char* kpmb = kpm + (size_t)b * Ssq;

    // load Q tile transposed: Qs[d][t]
#pragma unroll
    for (int tt = r; tt < QT; tt += 16) {
        float4 qv = *(const float4*)(qptr + (size_t)tt * Dd + d4);
        Qs[(d4 + 0) * QS_LD + tt] = qv.x;
        Qs[(d4 + 1) * QS_LD + tt] = qv.y;
        Qs[(d4 + 2) * QS_LD + tt] = qv.z;
        Qs[(d4 + 3) * QS_LD + tt] = qv.w;
    }
    if (tid < QT) { m_s[tid] = -3.0e38f; l_s[tid] = 0.f; }

    float acc[4][4];
#pragma unroll
    for (int i = 0; i < 4; i++)
#pragma unroll
        for (int j = 0; j < 4; j++) acc[i][j] = 0.f;

    for (int s0 = 0; s0 < Ssq; s0 += SC) {
        __syncthreads();  // protect Ks/Vs/Ps reuse vs previous iteration
        // load K chunk transposed, V chunk direct
        for (int ssr = r; ssr < SC; ssr += 16) {
            float4 kv = *(const float4*)(kbase + (size_t)(s0 + ssr) * Dd + d4);
            Ks[(d4 + 0) * KS_LD + ssr] = kv.x;
            Ks[(d4 + 1) * KS_LD + ssr] = kv.y;
            Ks[(d4 + 2) * KS_LD + ssr] = kv.z;
            Ks[(d4 + 3) * KS_LD + ssr] = kv.w;
            *(float4*)&Vs[ssr * Dd + d4] =
                *(const float4*)(vbase + (size_t)(s0 + ssr) * Dd + d4);
        }
        __syncthreads();

        // scores: st[i][j] = sum_d q[t0+ty*4+i][d] * k[s0+tx+16j][d]
        float st[4][8];
#pragma unroll
        for (int i = 0; i < 4; i++)
#pragma unroll
            for (int j = 0; j < 8; j++) st[i][j] = 0.f;

#pragma unroll 8
        for (int d = 0; d < Dd; d++) {
            float4 aq = *(const float4*)&Qs[d * QS_LD + ty * 4];
#pragma unroll
            for (int j = 0; j < 8; j++) {
                float bv = Ks[d * KS_LD + tx + 16 * j];
                st[0][j] = fmaf(aq.x, bv, st[0][j]);
                st[1][j] = fmaf(aq.y, bv, st[1][j]);
                st[2][j] = fmaf(aq.z, bv, st[2][j]);
                st[3][j] = fmaf(aq.w, bv, st[3][j]);
            }
        }

        // masks
#pragma unroll
        for (int j = 0; j < 8; j++) {
            int sg = s0 + tx + 16 * j;
            bool km = kpmb[sg] != 0;
#pragma unroll
            for (int i = 0; i < 4; i++) {
                int tg = t0 + ty * 4 + i;
                if (km || amask[(size_t)tg * Ssq + sg]) st[i][j] = -1e30f;
            }
        }

        // store raw (masked) scores; normalized later
        if (attnw) {
#pragma unroll
            for (int i = 0; i < 4; i++) {
                size_t base =
                    ((size_t)((b * Hh + h) * Tt) + t0 + ty * 4 + i) * Ssq + s0 + tx;
#pragma unroll
                for (int j = 0; j < 8; j++) attnw[base + 16 * j] = st[i][j];
            }
        }

        // chunk row max
#pragma unroll
        for (int i = 0; i < 4; i++) {
            float mx = st[i][0];
#pragma unroll
            for (int j = 1; j < 8; j++) mx = fmaxf(mx, st[i][j]);
            red[(ty * 4 + i) * RED_LD + tx] = mx;
        }
        __syncthreads();
        if (tid < QT) {
            float cm = red[tid * RED_LD];
#pragma unroll
            for (int x = 1; x < 16; x++) cm = fmaxf(cm, red[tid * RED_LD + x]);
            float mo = m_s[tid];
            float mn = fmaxf(mo, cm);
            float f  = __expf(mo - mn);
            m_s[tid] = mn; f_s[tid] = f; l_s[tid] *= f;
        }
        __syncthreads();

        // p = exp(s - m), rescale acc, partial row sums, stage P transposed
#pragma unroll
        for (int i = 0; i < 4; i++) {
            int row = ty * 4 + i;
            float mn = m_s[row];
            float f  = f_s[row];
#pragma unroll
            for (int j = 0; j < 4; j++) acc[i][j] *= f;
            float s = 0.f;
#pragma unroll
            for (int j = 0; j < 8; j++) {
                float p = __expf(st[i][j] - mn);
                Ps[(tx + 16 * j) * PS_LD + row] = p;
                s += p;
            }
            red[row * RED_LD + tx] = s;
        }
        __syncthreads();
        if (tid < QT) {
            float s = 0.f;
#pragma unroll
            for (int x = 0; x < 16; x++) s += red[tid * RED_LD + x];
            l_s[tid] += s;
        }

        // PV: acc[t][d] += P[t][s] * V[s][d]
#pragma unroll 4
        for (int ss2 = 0; ss2 < SC; ss2++) {
            float a0 = Ps[ss2 * PS_LD + ty * 4 + 0];
            float a1 = Ps[ss2 * PS_LD + ty * 4 + 1];
            float a2 = Ps[ss2 * PS_LD + ty * 4 + 2];
            float a3 = Ps[ss2 * PS_LD + ty * 4 + 3];
#pragma unroll
            for (int j = 0; j < 4; j++) {
                float bv = Vs[ss2 * Dd + tx + 16 * j];
                acc[0][j] = fmaf(a0, bv, acc[0][j]);
                acc[1][j] = fmaf(a1, bv, acc[1][j]);
                acc[2][j] = fmaf(a2, bv, acc[2][j]);
                acc[3][j] = fmaf(a3, bv, acc[3][j]);
            }
        }
    }

    __syncthreads();
#pragma unroll
    for (int i = 0; i < 4; i++) {
        int t = t0 + ty * 4 + i;
        float invl = 1.f / l_s[ty * 4 + i];
        size_t base = ((size_t)b * Tt + t) * Ee + h * Dd;
#pragma unroll
        for (int j = 0; j < 4; j++)
            g_attnout[base + tx + 16 * j] = acc[i][j] * invl;
    }
    if (tid < QT) {
        size_t row = (size_t)(b * Hh + h) * Tt + t0 + tid;
        g_rowm[row] = m_s[tid];
        g_rowl[row] = l_s[tid];
    }
}

// ---------------- normalize raw scores -> softmax weights, in place ----------------
__global__ void normalize_attn(float* __restrict__ attnw)
{
    const size_t n4 = (size_t)Bb * Hh * Tt * Ssq / 4;
    float4* a4 = (float4*)attnw;
    for (size_t i = (size_t)blockIdx.x * blockDim.x + threadIdx.x; i < n4;
         i += (size_t)gridDim.x * blockDim.x) {
        size_t row = (i * 4) / Ssq;
        float m = g_rowm[row];
        float invl = 1.f / g_rowl[row];
        float4 v = a4[i];
        v.x = __expf(v.x - m) * invl;
        v.y = __expf(v.y - m) * invl;
        v.z = __expf(v.z - m) * invl;
        v.w = __expf(v.w - m) * invl;
        a4[i] = v;
    }
}

// ---------------- launch ----------------
extern "C" void kernel_launch(void* const* d_in, const int* in_sizes, int n_in,
                              void* d_out, int out_size)
{
    const float* query = (const float*)d_in[0];
    const float* key   = (const float*)d_in[1];
    const float* value = (const float*)d_in[2];
    const unsigned char* kpm = (const unsigned char*)d_in[3];
    const unsigned char* am  = (const unsigned char*)d_in[4];
    const float* Wq = (const float*)d_in[5];  const float* bq = (const float*)d_in[6];
    const float* Wk = (const float*)d_in[7];  const float* bk = (const float*)d_in[8];
    const float* Wv = (const float*)d_in[9];  const float* bv = (const float*)d_in[10];
    const float* Wo = (const float*)d_in[11]; const float* bo = (const float*)d_in[12];

    float *qp, *kp, *vp, *aop;
    cudaGetSymbolAddress((void**)&qp,  g_q);
    cudaGetSymbolAddress((void**)&kp,  g_k);
    cudaGetSymbolAddress((void**)&vp,  g_v);
    cudaGetSymbolAddress((void**)&aop, g_attnout);

    const long long OUT_E  = (long long)Bb * Tt * Ee;                 // 4,194,304
    const long long ATTN_E = (long long)Bb * Hh * Tt * (long long)Ssq; // 134,217,728
    float* out_main = nullptr;
    float* out_attn = nullptr;
    if ((long long)out_size >= OUT_E + ATTN_E) {
        out_main = (float*)d_out;
        out_attn = (float*)d_out + OUT_E;
    } else if ((long long)out_size == ATTN_E) {
        out_attn = (float*)d_out;
    } else {
        out_main = (float*)d_out;
    }

    dim3 pg(Ee / BN, BT / BM);  // (4, 64)

    // projections (head-split layout; Q pre-scaled by Dh^-0.5)
    sgemm_bias<<<pg, 256>>>(query, Wq, bq, qp, 0.125f, 1);
    sgemm_bias<<<pg, 256>>>(key,   Wk, bk, kp, 1.0f,   1);
    sgemm_bias<<<pg, 256>>>(value, Wv, bv, vp, 1.0f,   1);

    // fused attention
    cudaFuncSetAttribute(attn_kernel, cudaFuncAttributeMaxDynamicSharedMemorySize,
                         ATT_SMEM_BYTES);
    dim3 ag(Tt / QT, Hh, Bb);  // (32, 8, 4)
    attn_kernel<<<ag, 256, ATT_SMEM_BYTES>>>(kpm, am, out_attn);

    if (out_attn) normalize_attn<<<2048, 256>>>(out_attn);

    if (out_main) sgemm_bias<<<pg, 256>>>(aop, Wo, bo, out_main, 1.0f, 0);
}

// round 8
// speedup vs baseline: 1.2259x; 1.2259x over previous
#include <cuda_runtime.h>

// ---------------- problem constants ----------------
constexpr int Bb = 4, Tt = 2048, Ssq = 2048, Ee = 512, Hh = 8, Dd = 64;
constexpr int BT = Bb * Tt;

// ---------------- device scratch (no cudaMalloc allowed) ----------------
__device__ float g_q[(size_t)Bb * Hh * Tt * Dd];       // [B,H,T,64], pre-scaled
__device__ float g_k[(size_t)Bb * Hh * Ssq * Dd];      // [B,H,S,64]
__device__ float g_v[(size_t)Bb * Hh * Ssq * Dd];      // [B,H,S,64]
__device__ float g_attnout[(size_t)BT * Ee];           // [B,T,E] pre-output-proj
__device__ float g_rowm[(size_t)Bb * Hh * Tt];         // per-row softmax max
__device__ float g_rowl[(size_t)Bb * Hh * Tt];         // per-row softmax denom

// ---------------- SGEMM: C = A[M,K] @ W[K,N] + bias, optional head layout ----------------
constexpr int BM = 128, BN = 128, BKk = 8, TM = 8, TN = 8;

__global__ __launch_bounds__(256, 2) void sgemm_bias(
    const float* __restrict__ A, const float* __restrict__ W,
    const float* __restrict__ bias, float* __restrict__ C,
    float scale, int head_layout)
{
    __shared__ float As[BKk][BM];
    __shared__ float Ws[BKk][BN];
    const int K = Ee, N = Ee;
    const int tid  = threadIdx.x;
    const int tcol = tid & 15;        // 16 col-groups
    const int trow = tid >> 4;        // 16 row-groups
    const int aRow = tid >> 1;        // 0..127
    const int aCol = (tid & 1) * 4;   // 0 or 4
    const int wRow = tid >> 5;        // 0..7
    const int wCol = (tid & 31) * 4;  // 0..124

    const float* Ab = A + (size_t)blockIdx.y * BM * K;
    const float* Wb = W + blockIdx.x * BN;

    float acc[TM][TN];
#pragma unroll
    for (int i = 0; i < TM; i++)
#pragma unroll
        for (int j = 0; j < TN; j++) acc[i][j] = 0.f;

    for (int k0 = 0; k0 < K; k0 += BKk) {
        float4 av = *(const float4*)(Ab + (size_t)aRow * K + k0 + aCol);
        As[aCol + 0][aRow] = av.x;
        As[aCol + 1][aRow] = av.y;
        As[aCol + 2][aRow] = av.z;
        As[aCol + 3][aRow] = av.w;
        *(float4*)(&Ws[wRow][wCol]) = *(const float4*)(Wb + (size_t)(k0 + wRow) * N + wCol);
        __syncthreads();
#pragma unroll
        for (int k = 0; k < BKk; k++) {
            float4 a0 = *(const float4*)&As[k][trow * TM];
            float4 a1 = *(const float4*)&As[k][trow * TM + 4];
            float4 b0 = *(const float4*)&Ws[k][tcol * TN];
            float4 b1 = *(const float4*)&Ws[k][tcol * TN + 4];
            float ar[8] = {a0.x, a0.y, a0.z, a0.w, a1.x, a1.y, a1.z, a1.w};
            float br[8] = {b0.x, b0.y, b0.z, b0.w, b1.x, b1.y, b1.z, b1.w};
#pragma unroll
            for (int i = 0; i < TM; i++)
#pragma unroll
                for (int j = 0; j < TN; j++) acc[i][j] = fmaf(ar[i], br[j], acc[i][j]);
        }
        __syncthreads();
    }

#pragma unroll
    for (int i = 0; i < TM; i++) {
        int m = blockIdx.y * BM + trow * TM + i;
        int b = m / Tt, t = m % Tt;
#pragma unroll
        for (int j = 0; j < TN; j++) {
            int n = blockIdx.x * BN + tcol * TN + j;
            float v = (acc[i][j] + bias[n]) * scale;
            if (head_layout) {
                int h = n >> 6, d = n & 63;
                C[((size_t)(b * Hh + h) * Tt + t) * Dd + d] = v;
            } else {
                C[(size_t)m * N + n] = v;
            }
        }
    }
}

// ---------------- fused attention: QK^T + masks + raw-score store + online softmax + PV ----------------
// SMEM budget: Ps is ALIASED onto Ks (disjoint lifetimes within a chunk iteration),
// bringing per-CTA smem to ~88KB so 2 CTAs fit per SM (occupancy 12.5% -> 25%).
constexpr int QT = 64, SC = 128;
constexpr int QS_LD = 68, KS_LD = 129, PS_LD = 68, RED_LD = 17;
constexpr int KSPS_FLOATS = (SC * PS_LD > Dd * KS_LD) ? SC * PS_LD : Dd * KS_LD;  // 8704
constexpr int ATT_SMEM_FLOATS =
    Dd * QS_LD + KSPS_FLOATS + SC * Dd + QT * RED_LD + 3 * QT;   // 22528 floats
constexpr int ATT_SMEM_BYTES = ATT_SMEM_FLOATS * 4;              // 90112 B

__global__ __launch_bounds__(256, 2) void attn_kernel(
    const unsigned char* __restrict__ kpm,    // [B,S] bool
    const unsigned char* __restrict__ amask,  // [T,S] bool
    float* __restrict__ attnw)                // raw-score scratch / attn output (may be null)
{
    extern __shared__ float sm[];
    float* Qs  = sm;                     // [Dd][QS_LD]    q transposed (d-major)
    float* Ks  = Qs + Dd * QS_LD;        // [Dd][KS_LD]    k transposed (d-major)
    float* Ps  = Ks;                     // [SC][PS_LD]    ALIAS: p transposed (s-major)
    float* Vs  = Ks + KSPS_FLOATS;       // [SC][Dd]
    float* red = Vs + SC * Dd;           // [QT][RED_LD]
    float* m_s = red + QT * RED_LD;      // [QT]
    float* l_s = m_s + QT;               // [QT]
    float* f_s = l_s + QT;               // [QT]

    const int b  = blockIdx.z, h = blockIdx.y;
    const int t0 = blockIdx.x * QT;
    const int tid = threadIdx.x;
    const int tx  = tid & 15, ty = tid >> 4;
    const int r   = tid >> 4;
    const int d4  = (tid & 15) * 4;

    const float* qptr  = g_q + ((size_t)(b * Hh + h) * Tt + t0) * Dd;
    const float* kbase = g_k + (size_t)(b * Hh + h) * Ssq * Dd;
    const float* vbase = g_v + (size_t)(b * Hh + h) * Ssq * Dd;
    const unsigned char* kpmb = kpm + (size_t)b * Ssq;

    // load Q tile transposed: Qs[d][t]
#pragma unroll
    for (int tt = r; tt < QT; tt += 16) {
        float4 qv = *(const float4*)(qptr + (size_t)tt * Dd + d4);
        Qs[(d4 + 0) * QS_LD + tt] = qv.x;
        Qs[(d4 + 1) * QS_LD + tt] = qv.y;
        Qs[(d4 + 2) * QS_LD + tt] = qv.z;
        Qs[(d4 + 3) * QS_LD + tt] = qv.w;
    }
    if (tid < QT) { m_s[tid] = -3.0e38f; l_s[tid] = 0.f; }

    // acc[i][j]: output rows t0 + ty*4 + i, head dims tx*4 + j (vector-friendly)
    float acc[4][4];
#pragma unroll
    for (int i = 0; i < 4; i++)
#pragma unroll
        for (int j = 0; j < 4; j++) acc[i][j] = 0.f;

    for (int s0 = 0; s0 < Ssq; s0 += SC) {
        __syncthreads();  // previous iteration's Ps (alias of Ks) / Vs reads done
        // load K chunk transposed, V chunk direct
        for (int ssr = r; ssr < SC; ssr += 16) {
            float4 kv = *(const float4*)(kbase + (size_t)(s0 + ssr) * Dd + d4);
            Ks[(d4 + 0) * KS_LD + ssr] = kv.x;
            Ks[(d4 + 1) * KS_LD + ssr] = kv.y;
            Ks[(d4 + 2) * KS_LD + ssr] = kv.z;
            Ks[(d4 + 3) * KS_LD + ssr] = kv.w;
            *(float4*)&Vs[ssr * Dd + d4] =
                *(const float4*)(vbase + (size_t)(s0 + ssr) * Dd + d4);
        }
        __syncthreads();

        // scores: st[i][j] = sum_d q[t0+ty*4+i][d] * k[s0+tx+16j][d]
        float st[4][8];
#pragma unroll
        for (int i = 0; i < 4; i++)
#pragma unroll
            for (int j = 0; j < 8; j++) st[i][j] = 0.f;

#pragma unroll 8
        for (int d = 0; d < Dd; d++) {
            float4 aq = *(const float4*)&Qs[d * QS_LD + ty * 4];
#pragma unroll
            for (int j = 0; j < 8; j++) {
                float bv = Ks[d * KS_LD + tx + 16 * j];
                st[0][j] = fmaf(aq.x, bv, st[0][j]);
                st[1][j] = fmaf(aq.y, bv, st[1][j]);
                st[2][j] = fmaf(aq.z, bv, st[2][j]);
                st[3][j] = fmaf(aq.w, bv, st[3][j]);
            }
        }

        // masks
#pragma unroll
        for (int j = 0; j < 8; j++) {
            int sg = s0 + tx + 16 * j;
            bool km = kpmb[sg] != 0;
#pragma unroll
            for (int i = 0; i < 4; i++) {
                int tg = t0 + ty * 4 + i;
                if (km || amask[(size_t)tg * Ssq + sg]) st[i][j] = -1e30f;
            }
        }

        // store raw (masked) scores; normalized later
        if (attnw) {
#pragma unroll
            for (int i = 0; i < 4; i++) {
                size_t base =
                    ((size_t)((b * Hh + h) * Tt) + t0 + ty * 4 + i) * Ssq + s0 + tx;
#pragma unroll
                for (int j = 0; j < 8; j++) attnw[base + 16 * j] = st[i][j];
            }
        }

        // chunk row max
#pragma unroll
        for (int i = 0; i < 4; i++) {
            float mx = st[i][0];
#pragma unroll
            for (int j = 1; j < 8; j++) mx = fmaxf(mx, st[i][j]);
            red[(ty * 4 + i) * RED_LD + tx] = mx;
        }
        __syncthreads();   // also: last Ks reads complete before Ps overwrite below
        if (tid < QT) {
            float cm = red[tid * RED_LD];
#pragma unroll
            for (int x = 1; x < 16; x++) cm = fmaxf(cm, red[tid * RED_LD + x]);
            float mo = m_s[tid];
            float mn = fmaxf(mo, cm);
            float f  = __expf(mo - mn);
            m_s[tid] = mn; f_s[tid] = f; l_s[tid] *= f;
        }
        __syncthreads();

        // p = exp(s - m), rescale acc, partial row sums, stage P transposed (into Ks alias)
#pragma unroll
        for (int i = 0; i < 4; i++) {
            int row = ty * 4 + i;
            float mn = m_s[row];
            float f  = f_s[row];
#pragma unroll
            for (int j = 0; j < 4; j++) acc[i][j] *= f;
            float s = 0.f;
#pragma unroll
            for (int j = 0; j < 8; j++) {
                float p = __expf(st[i][j] - mn);
                Ps[(tx + 16 * j) * PS_LD + row] = p;
                s += p;
            }
            red[row * RED_LD + tx] = s;
        }
        __syncthreads();
        if (tid < QT) {
            float s = 0.f;
#pragma unroll
            for (int x = 0; x < 16; x++) s += red[tid * RED_LD + x];
            l_s[tid] += s;
        }

        // PV: acc[i][j] += P[t][s] * V[s][d], d = tx*4 + j — vectorized LDS.128
#pragma unroll 4
        for (int ss2 = 0; ss2 < SC; ss2++) {
            float4 pa = *(const float4*)&Ps[ss2 * PS_LD + ty * 4];
            float4 vb = *(const float4*)&Vs[ss2 * Dd + tx * 4];
            float pr[4] = {pa.x, pa.y, pa.z, pa.w};
            float vr[4] = {vb.x, vb.y, vb.z, vb.w};
#pragma unroll
            for (int i = 0; i < 4; i++)
#pragma unroll
                for (int j = 0; j < 4; j++)
                    acc[i][j] = fmaf(pr[i], vr[j], acc[i][j]);
        }
    }

    __syncthreads();
#pragma unroll
    for (int i = 0; i < 4; i++) {
        int t = t0 + ty * 4 + i;
        float invl = 1.f / l_s[ty * 4 + i];
        size_t base = ((size_t)b * Tt + t) * Ee + h * Dd;
        float4 o;
        o.x = acc[i][0] * invl;
        o.y = acc[i][1] * invl;
        o.z = acc[i][2] * invl;
        o.w = acc[i][3] * invl;
        *(float4*)&g_attnout[base + tx * 4] = o;
    }
    if (tid < QT) {
        size_t row = (size_t)(b * Hh + h) * Tt + t0 + tid;
        g_rowm[row] = m_s[tid];
        g_rowl[row] = l_s[tid];
    }
}

// ---------------- normalize raw scores -> softmax weights, in place ----------------
__global__ void normalize_attn(float* __restrict__ attnw)
{
    const size_t n4 = (size_t)Bb * Hh * Tt * Ssq / 4;
    float4* a4 = (float4*)attnw;
    for (size_t i = (size_t)blockIdx.x * blockDim.x + threadIdx.x; i < n4;
         i += (size_t)gridDim.x * blockDim.x) {
        size_t row = (i * 4) / Ssq;
        float m = g_rowm[row];
        float invl = 1.f / g_rowl[row];
        float4 v = a4[i];
        v.x = __expf(v.x - m) * invl;
        v.y = __expf(v.y - m) * invl;
        v.z = __expf(v.z - m) * invl;
        v.w = __expf(v.w - m) * invl;
        a4[i] = v;
    }
}

// ---------------- launch ----------------
extern "C" void kernel_launch(void* const* d_in, const int* in_sizes, int n_in,
                              void* d_out, int out_size)
{
    const float* query = (const float*)d_in[0];
    const float* key   = (const float*)d_in[1];
    const float* value = (const float*)d_in[2];
    const unsigned char* kpm = (const unsigned char*)d_in[3];
    const unsigned char* am  = (const unsigned char*)d_in[4];
    const float* Wq = (const float*)d_in[5];  const float* bq = (const float*)d_in[6];
    const float* Wk = (const float*)d_in[7];  const float* bk = (const float*)d_in[8];
    const float* Wv = (const float*)d_in[9];  const float* bv = (const float*)d_in[10];
    const float* Wo = (const float*)d_in[11]; const float* bo = (const float*)d_in[12];

    float *qp, *kp, *vp, *aop;
    cudaGetSymbolAddress((void**)&qp,  g_q);
    cudaGetSymbolAddress((void**)&kp,  g_k);
    cudaGetSymbolAddress((void**)&vp,  g_v);
    cudaGetSymbolAddress((void**)&aop, g_attnout);

    const long long OUT_E  = (long long)Bb * Tt * Ee;                  // 4,194,304
    const long long ATTN_E = (long long)Bb * Hh * Tt * (long long)Ssq; // 134,217,728
    float* out_main = nullptr;
    float* out_attn = nullptr;
    if ((long long)out_size >= OUT_E + ATTN_E) {
        out_main = (float*)d_out;
        out_attn = (float*)d_out + OUT_E;
    } else if ((long long)out_size == ATTN_E) {
        out_attn = (float*)d_out;
    } else {
        out_main = (float*)d_out;
    }

    dim3 pg(Ee / BN, BT / BM);  // (4, 64)

    // projections (head-split layout; Q pre-scaled by Dh^-0.5)
    sgemm_bias<<<pg, 256>>>(query, Wq, bq, qp, 0.125f, 1);
    sgemm_bias<<<pg, 256>>>(key,   Wk, bk, kp, 1.0f,   1);
    sgemm_bias<<<pg, 256>>>(value, Wv, bv, vp, 1.0f,   1);

    // fused attention (2 CTAs/SM thanks to Ps/Ks smem aliasing)
    cudaFuncSetAttribute(attn_kernel, cudaFuncAttributeMaxDynamicSharedMemorySize,
                         ATT_SMEM_BYTES);
    dim3 ag(Tt / QT, Hh, Bb);  // (32, 8, 4)
    attn_kernel<<<ag, 256, ATT_SMEM_BYTES>>>(kpm, am, out_attn);

    if (out_attn) normalize_attn<<<2048, 256>>>(out_attn);

    if (out_main) sgemm_bias<<<pg, 256>>>(aop, Wo, bo, out_main, 1.0f, 0);
}